// round 5
// baseline (speedup 1.0000x reference)
#include <cuda_runtime.h>
#include <cuda_bf16.h>
#include <cstdint>

#define NROWS 16384
#define KDIM  16384
#define NCOLS 64
#define KC    64
#define NCHUNK (KDIM / KC)

// -------- device scratch --------
__device__ __align__(256) float    g_sup[(size_t)NROWS * NCOLS];
// B in MMA fragment layout: [wn(2)][chunk(256)][khalf(2)][lane(32)][reg(16)] u32
__device__ __align__(256) uint32_t g_bhi[2u * NCHUNK * 2 * 32 * 16];
__device__ __align__(256) uint32_t g_blo[2u * NCHUNK * 2 * 32 * 16];

// -------- helpers --------
__device__ __forceinline__ uint32_t smem_u32(const void* p) {
    uint32_t a;
    asm("{ .reg .u64 t; cvta.to.shared.u64 t, %1; cvt.u32.u64 %0, t; }" : "=r"(a) : "l"(p));
    return a;
}
__device__ __forceinline__ uint32_t sw128(uint32_t off) { return off ^ ((off >> 3) & 0x70); }

__device__ __forceinline__ uint32_t pack2(float a, float b) {   // a -> LOW half
    uint32_t r;
    asm("cvt.rn.bf16x2.f32 %0, %1, %2;" : "=r"(r) : "f"(b), "f"(a));
    return r;
}
__device__ __forceinline__ float2 unpack2(uint32_t u) {
    __nv_bfloat162 h = *reinterpret_cast<__nv_bfloat162*>(&u);
    return make_float2(__low2float(h), __high2float(h));
}
__device__ __forceinline__ uint32_t prmt_hi(uint32_t u0, uint32_t u1) {
    uint32_t r;
    asm("prmt.b32 %0, %1, %2, 0x7632;" : "=r"(r) : "r"(u0), "r"(u1));
    return r;
}
__device__ __forceinline__ void sts128(uint32_t addr, uint32_t a, uint32_t b, uint32_t c, uint32_t d) {
    asm volatile("st.shared.v4.b32 [%0], {%1,%2,%3,%4};"
                 :: "r"(addr), "r"(a), "r"(b), "r"(c), "r"(d) : "memory");
}
__device__ __forceinline__ void lds128f(uint32_t addr, float* v) {
    asm volatile("ld.shared.v4.f32 {%0,%1,%2,%3}, [%4];"
                 : "=f"(v[0]), "=f"(v[1]), "=f"(v[2]), "=f"(v[3]) : "r"(addr));
}

#define LDSM4(r, addr) \
    asm volatile("ldmatrix.sync.aligned.m8n8.x4.shared.b16 {%0,%1,%2,%3}, [%4];" \
                 : "=r"((r)[0]), "=r"((r)[1]), "=r"((r)[2]), "=r"((r)[3]) : "r"(addr))

#define MMA16816(d, a, b0_, b1_) \
    asm volatile("mma.sync.aligned.m16n8k16.row.col.f32.bf16.bf16.f32 " \
                 "{%0,%1,%2,%3}, {%4,%5,%6,%7}, {%8,%9}, {%0,%1,%2,%3};" \
                 : "+f"((d)[0]), "+f"((d)[1]), "+f"((d)[2]), "+f"((d)[3]) \
                 : "r"((a)[0]), "r"((a)[1]), "r"((a)[2]), "r"((a)[3]), \
                   "r"(b0_), "r"(b1_))

// -------- prep: support = x @ W ; store fp32 + B fragments (hi/lo) --------
__global__ __launch_bounds__(256) void gcn_prep(const float* __restrict__ x,
                                                const float* __restrict__ W) {
    int tid = threadIdx.x;
    int rg = tid & 31, cg = tid >> 5;
    int row0 = blockIdx.x * 128 + rg * 4;   // k dimension of support^T
    int c0 = cg * 8;                         // n dimension
    float acc[4][8];
#pragma unroll
    for (int i = 0; i < 4; i++)
#pragma unroll
        for (int j = 0; j < 8; j++) acc[i][j] = 0.f;

    const float4* x4 = reinterpret_cast<const float4*>(x);
    const float4* W4 = reinterpret_cast<const float4*>(W);

    for (int k4 = 0; k4 < 64; k4++) {
        float4 xv[4];
#pragma unroll
        for (int i = 0; i < 4; i++) xv[i] = __ldg(&x4[(size_t)(row0 + i) * 64 + k4]);
#pragma unroll
        for (int j = 0; j < 4; j++) {
            float4 wa = __ldg(&W4[(k4 * 4 + j) * 16 + cg * 2]);
            float4 wb = __ldg(&W4[(k4 * 4 + j) * 16 + cg * 2 + 1]);
#pragma unroll
            for (int i = 0; i < 4; i++) {
                float xs = (j == 0) ? xv[i].x : (j == 1) ? xv[i].y : (j == 2) ? xv[i].z : xv[i].w;
                acc[i][0] = fmaf(xs, wa.x, acc[i][0]);
                acc[i][1] = fmaf(xs, wa.y, acc[i][1]);
                acc[i][2] = fmaf(xs, wa.z, acc[i][2]);
                acc[i][3] = fmaf(xs, wa.w, acc[i][3]);
                acc[i][4] = fmaf(xs, wb.x, acc[i][4]);
                acc[i][5] = fmaf(xs, wb.y, acc[i][5]);
                acc[i][6] = fmaf(xs, wb.z, acc[i][6]);
                acc[i][7] = fmaf(xs, wb.w, acc[i][7]);
            }
        }
    }
#pragma unroll
    for (int i = 0; i < 4; i++) {
        float* sp = g_sup + (size_t)(row0 + i) * NCOLS + c0;
        reinterpret_cast<float4*>(sp)[0] = make_float4(acc[i][0], acc[i][1], acc[i][2], acc[i][3]);
        reinterpret_cast<float4*>(sp)[1] = make_float4(acc[i][4], acc[i][5], acc[i][6], acc[i][7]);
    }
    // B fragment store: k = row0..row0+3, n = c0..c0+7
    int cch   = row0 >> 6;
    int khalf = (row0 >> 5) & 1;
    int ks    = (row0 >> 4) & 1;
    int kk0   = row0 & 15;
    int b1    = (kk0 >= 8) ? 1 : 0;
    int p0    = (kk0 & 7) >> 1;
#pragma unroll
    for (int j = 0; j < 8; j++) {
        int n = c0 + j;
        int wn = n >> 5, nt = (n >> 3) & 3;
        int reg = ks * 8 + nt * 2 + b1;
        int lane0 = (n & 7) * 4 + p0;
        size_t base = ((((size_t)wn * NCHUNK + cch) * 2 + khalf) * 32) * 16;
        uint32_t h0 = pack2(acc[0][j], acc[1][j]);
        uint32_t h1 = pack2(acc[2][j], acc[3][j]);
        float2 f0 = unpack2(h0), f1 = unpack2(h1);
        uint32_t l0 = pack2(acc[0][j] - f0.x, acc[1][j] - f0.y);
        uint32_t l1 = pack2(acc[2][j] - f1.x, acc[3][j] - f1.y);
        g_bhi[base + (size_t)lane0 * 16 + reg] = h0;
        g_bhi[base + (size_t)(lane0 + 1) * 16 + reg] = h1;
        g_blo[base + (size_t)lane0 * 16 + reg] = l0;
        g_blo[base + (size_t)(lane0 + 1) * 16 + reg] = l1;
    }
}

// -------- main --------
// 128 CTAs x 128 rows, 512 threads. Warp grid 4m x 2n x 2k; warp tile 32x32 over K/2.
#define STAGE_BYTES 32768   // A_hi 16K | A_lo 16K
#define SMEM_MAIN   (1024 + 2 * STAGE_BYTES)

__device__ __forceinline__ void stage_A(uint32_t A_hi, uint32_t A_lo,
                                        const float* f, uint32_t abase) {
    const uint32_t* u = reinterpret_cast<const uint32_t*>(f);
#pragma unroll
    for (int q = 0; q < 2; q++) {
        uint32_t wh[4], wl[4];
#pragma unroll
        for (int i = 0; i < 4; i++) {
            uint32_t u0 = u[q * 8 + 2 * i], u1 = u[q * 8 + 2 * i + 1];
            wh[i] = prmt_hi(u0, u1);
            float l0 = f[q * 8 + 2 * i]     - __uint_as_float(u0 & 0xFFFF0000u);
            float l1 = f[q * 8 + 2 * i + 1] - __uint_as_float(u1 & 0xFFFF0000u);
            wl[i] = pack2(l0, l1);
        }
        uint32_t off = sw128(abase + q * 16);
        sts128(A_hi + off, wh[0], wh[1], wh[2], wh[3]);
        sts128(A_lo + off, wl[0], wl[1], wl[2], wl[3]);
    }
}

__global__ __launch_bounds__(512, 1) void gcn_main(const float* __restrict__ adj,
                                                   const float* __restrict__ bias,
                                                   float* __restrict__ out) {
    extern __shared__ char dsm[];
    uint32_t sbase = smem_u32(dsm);
    uint32_t tiles = (sbase + 1023) & ~1023u;
    int tid = threadIdx.x;
    int wid = tid >> 5;
    int lane = tid & 31;
    int row0 = blockIdx.x * 128;
    int wm = wid & 3, wn = (wid >> 2) & 1, wk = wid >> 3;

    // A loader mapping: 128 rows x 4 segs of 16 floats
    int arow = tid >> 2, aseg = tid & 3;
    uint32_t abase = (uint32_t)arow * 128 + (uint32_t)aseg * 32;

    // ldmatrix per-lane offsets (A)
    uint32_t a_r  = ((lane >> 3) & 1) * 8 + (lane & 7);
    uint32_t a_kh = (lane >> 4) & 1;
    uint32_t arowb[2];
#pragma unroll
    for (int mt = 0; mt < 2; mt++) arowb[mt] = (wm * 32 + mt * 16 + a_r) * 128;

    float acc[2][4][4];
#pragma unroll
    for (int mt = 0; mt < 2; mt++)
#pragma unroll
        for (int nt = 0; nt < 4; nt++)
#pragma unroll
            for (int j = 0; j < 4; j++) acc[mt][nt][j] = 0.f;

    const float4* apbase = reinterpret_cast<const float4*>(
        adj + (size_t)(row0 + arow) * KDIM + aseg * 16);
    const uint32_t* bhp = g_bhi + (((size_t)wn * NCHUNK) * 2 + wk) * 512 + (size_t)lane * 16;
    const uint32_t* blp = g_blo + (((size_t)wn * NCHUNK) * 2 + wk) * 512 + (size_t)lane * 16;

    // ---- prologue: stage chunk 0 ----
    {
        float av[16];
#pragma unroll
        for (int q = 0; q < 4; q++)
            reinterpret_cast<float4*>(av)[q] = apbase[q];
        stage_A(tiles, tiles + 16384, av, abase);
    }
    __syncthreads();

    // ---- main loop ----
#pragma unroll 1
    for (int c = 0; c < NCHUNK; ++c) {
        int st = c & 1;
        uint32_t A_hi = tiles + st * STAGE_BYTES;
        uint32_t A_lo = A_hi + 16384;

        // prefetch A of chunk c+1 (HBM)
        float av[16];
        bool more = (c + 1 < NCHUNK);
        if (more) {
            const float4* ap = apbase + (size_t)(c + 1) * (KC / 4);
#pragma unroll
            for (int q = 0; q < 4; q++)
                reinterpret_cast<float4*>(av)[q] = ap[q];
        }

        const uint32_t* bh_c = bhp + (size_t)c * 1024;   // 2*512
        const uint32_t* bl_c = blp + (size_t)c * 1024;

        // MMA over this chunk's k-half
#pragma unroll
        for (int ks = 0; ks < 2; ks++) {
            uint32_t ak = (uint32_t)wk * 64 + (uint32_t)(ks * 32) + a_kh * 16;
            uint32_t ah[2][4], al[2][4];
#pragma unroll
            for (int mt = 0; mt < 2; mt++) {
                LDSM4(ah[mt], A_hi + sw128(arowb[mt] + ak));
                LDSM4(al[mt], A_lo + sw128(arowb[mt] + ak));
            }
            uint32_t bh[8], bl[8];
            {
                uint4 t0 = __ldg(reinterpret_cast<const uint4*>(bh_c + ks * 8));
                uint4 t1 = __ldg(reinterpret_cast<const uint4*>(bh_c + ks * 8 + 4));
                bh[0]=t0.x; bh[1]=t0.y; bh[2]=t0.z; bh[3]=t0.w;
                bh[4]=t1.x; bh[5]=t1.y; bh[6]=t1.z; bh[7]=t1.w;
                uint4 s0 = __ldg(reinterpret_cast<const uint4*>(bl_c + ks * 8));
                uint4 s1 = __ldg(reinterpret_cast<const uint4*>(bl_c + ks * 8 + 4));
                bl[0]=s0.x; bl[1]=s0.y; bl[2]=s0.z; bl[3]=s0.w;
                bl[4]=s1.x; bl[5]=s1.y; bl[6]=s1.z; bl[7]=s1.w;
            }
#pragma unroll
            for (int mt = 0; mt < 2; mt++) {
#pragma unroll
                for (int nt = 0; nt < 4; nt++) {
                    MMA16816(acc[mt][nt], ah[mt], bh[nt * 2], bh[nt * 2 + 1]);
                    MMA16816(acc[mt][nt], ah[mt], bl[nt * 2], bl[nt * 2 + 1]);
                    MMA16816(acc[mt][nt], al[mt], bh[nt * 2], bh[nt * 2 + 1]);
                }
            }
        }

        if (more) {
            uint32_t Ah2 = tiles + (st ^ 1) * STAGE_BYTES;
            stage_A(Ah2, Ah2 + 16384, av, abase);
        }
        __syncthreads();
    }

    // ---- merge k-split partials: wk=1 warps dump accs to smem ----
    if (wk == 1) {
#pragma unroll
        for (int mt = 0; mt < 2; mt++)
#pragma unroll
            for (int nt = 0; nt < 4; nt++) {
                uint32_t off = tiles + (uint32_t)(wid & 7) * 4096 +
                               (uint32_t)(mt * 4 + nt) * 512 + (uint32_t)lane * 16;
                sts128(off, __float_as_uint(acc[mt][nt][0]), __float_as_uint(acc[mt][nt][1]),
                             __float_as_uint(acc[mt][nt][2]), __float_as_uint(acc[mt][nt][3]));
            }
    }
    __syncthreads();

    if (wk == 0) {
        int g = lane >> 2, t = lane & 3;
#pragma unroll
        for (int mt = 0; mt < 2; mt++) {
            int ra = row0 + wm * 32 + mt * 16 + g;
#pragma unroll
            for (int nt = 0; nt < 4; nt++) {
                float p[4];
                lds128f(tiles + (uint32_t)wid * 4096 + (uint32_t)(mt * 4 + nt) * 512 +
                        (uint32_t)lane * 16, p);
                int col = wn * 32 + nt * 8 + t * 2;
                float2 bb = *reinterpret_cast<const float2*>(bias + col);
                float2 s0 = *reinterpret_cast<const float2*>(g_sup + (size_t)ra * NCOLS + col);
                float2 s1 = *reinterpret_cast<const float2*>(g_sup + (size_t)(ra + 8) * NCOLS + col);
                float2 r0, r1;
                r0.x = fmaxf(acc[mt][nt][0] + p[0] + s0.x + bb.x, 0.f);
                r0.y = fmaxf(acc[mt][nt][1] + p[1] + s0.y + bb.y, 0.f);
                r1.x = fmaxf(acc[mt][nt][2] + p[2] + s1.x + bb.x, 0.f);
                r1.y = fmaxf(acc[mt][nt][3] + p[3] + s1.y + bb.y, 0.f);
                *reinterpret_cast<float2*>(out + (size_t)ra * NCOLS + col) = r0;
                *reinterpret_cast<float2*>(out + (size_t)(ra + 8) * NCOLS + col) = r1;
            }
        }
    }
}

extern "C" void kernel_launch(void* const* d_in, const int* in_sizes, int n_in,
                              void* d_out, int out_size) {
    const float *x = nullptr, *adj = nullptr, *W = nullptr, *b = nullptr;
    for (int i = 0; i < n_in; i++) {
        long s = in_sizes[i];
        if (s == (long)NROWS * 256)        x   = (const float*)d_in[i];
        else if (s == (long)NROWS * NROWS) adj = (const float*)d_in[i];
        else if (s == 256L * NCOLS)        W   = (const float*)d_in[i];
        else if (s == (long)NCOLS)         b   = (const float*)d_in[i];
    }
    cudaFuncSetAttribute(gcn_main, cudaFuncAttributeMaxDynamicSharedMemorySize, SMEM_MAIN);
    gcn_prep<<<128, 256>>>(x, W);
    gcn_main<<<128, 512, SMEM_MAIN>>>(adj, b, (float*)d_out);
}